// round 1
// baseline (speedup 1.0000x reference)
#include <cuda_runtime.h>
#include <math_constants.h>

// Problem constants (shapes fixed by the dataset)
#define LSEQ 2048
#define DDIM 768
#define KF   16
#define KU   3
#define NFFT 4096
#define RSPEC (2*KF*DDIM)        // 24576 spectral reduction rows
#define RTOT  (2*KF*DDIM + KU*DDIM)  // 26880 total reduction rows

// ---------------- device scratch (static, no allocations) ----------------
__device__ float  g_xT[DDIM*LSEQ];          // x transposed: (d, t)         6 MB
__device__ float2 g_Xf[DDIM*NFFT];          // full FFT of x per channel   25 MB
__device__ float2 g_Vf[KF*NFFT];            // full FFT of phi per filter 0.5 MB
__device__ float  g_Ucat[(size_t)RTOT*LSEQ]; // stacked reduction operand 220 MB
__device__ float  g_Mcat[(size_t)RTOT*DDIM]; // stacked projection matrix  82 MB

// ---------------- complex helpers ----------------
__device__ __forceinline__ float2 cmul(float2 a, float2 b) {
    return make_float2(a.x*b.x - a.y*b.y, a.x*b.y + a.y*b.x);
}

// ---------------- shared-memory 4096-pt complex FFT ----------------
// 512 threads. sh: 4096 float2 (natural order in/out). W: 2048 twiddles
// W[j] = exp(sign * 2*pi*i * j / 4096) pre-filled by caller.
__device__ __forceinline__ void fft4096_shared(float2* sh, const float2* W, int tid) {
    // bit-reversal permutation (12 bits)
    #pragma unroll
    for (int s = 0; s < 8; s++) {
        int i = tid + s*512;
        int j = (int)(__brev((unsigned)i) >> 20);
        if (j > i) { float2 a = sh[i]; sh[i] = sh[j]; sh[j] = a; }
    }
    __syncthreads();
    #pragma unroll
    for (int lp = 1; lp <= 12; lp++) {
        const int len   = 1 << lp;
        const int half  = len >> 1;
        const int shift = 12 - lp;
        #pragma unroll
        for (int s = 0; s < 4; s++) {
            int b   = tid + s*512;          // butterfly id in [0, 2048)
            int pos = b & (half - 1);
            int i0  = ((b & ~(half - 1)) << 1) | pos;
            int i1  = i0 + half;
            float2 w  = W[pos << shift];
            float2 u  = sh[i0];
            float2 v  = sh[i1];
            float2 wv = cmul(w, v);
            sh[i0] = make_float2(u.x + wv.x, u.y + wv.y);
            sh[i1] = make_float2(u.x - wv.x, u.y - wv.y);
        }
        __syncthreads();
    }
}

// ---------------- kernels ----------------

// x (t, d) -> g_xT (d, t)
__global__ void transpose_kernel(const float* __restrict__ x) {
    __shared__ float tile[32][33];
    int t0 = blockIdx.x * 32;
    int d0 = blockIdx.y * 32;
    int tx = threadIdx.x, ty = threadIdx.y;   // block (32, 8)
    #pragma unroll
    for (int s = 0; s < 32; s += 8)
        tile[ty + s][tx] = x[(t0 + ty + s) * DDIM + d0 + tx];
    __syncthreads();
    #pragma unroll
    for (int s = 0; s < 32; s += 8)
        g_xT[(size_t)(d0 + ty + s) * LSEQ + t0 + tx] = tile[tx][ty + s];
}

// Build Mcat: [sig4*Mp ; sig4*Mm ; Mu], row r = reduction index, col o
__global__ void mcat_kernel(const float* __restrict__ Mp,
                            const float* __restrict__ Mm,
                            const float* __restrict__ Mu,
                            const float* __restrict__ sigma) {
    int idx = blockIdx.x * blockDim.x + threadIdx.x;
    if (idx >= RTOT * DDIM) return;
    int r = idx / DDIM;
    int o = idx - r * DDIM;
    float v;
    if (r < KF*DDIM) {
        int k = r / DDIM, d = r - k*DDIM;
        v = Mp[((size_t)(k*DDIM + d)) * DDIM + o] * powf(sigma[k], 0.25f);
    } else if (r < 2*KF*DDIM) {
        int rr = r - KF*DDIM;
        int k = rr / DDIM, d = rr - k*DDIM;
        v = Mm[((size_t)(k*DDIM + d)) * DDIM + o] * powf(sigma[k], 0.25f);
    } else {
        int rr = r - 2*KF*DDIM;              // rr = i*DDIM + d
        v = Mu[(size_t)rr * DDIM + o];
    }
    g_Mcat[idx] = v;
}

// Forward FFT of each x channel (zero-padded to 4096). One block per d.
__global__ void __launch_bounds__(512) fft_x_kernel() {
    __shared__ float2 sh[NFFT];
    __shared__ float2 W[NFFT/2];
    int d = blockIdx.x, tid = threadIdx.x;
    #pragma unroll
    for (int s = 0; s < 4; s++) {
        int j = tid + s*512;
        float th = -2.0f * CUDART_PI_F * (float)j / (float)NFFT;
        float sn, cs; sincosf(th, &sn, &cs);
        W[j] = make_float2(cs, sn);
    }
    #pragma unroll
    for (int s = 0; s < 8; s++) {
        int t = tid + s*512;
        float v = (t < LSEQ) ? g_xT[(size_t)d * LSEQ + t] : 0.0f;
        sh[t] = make_float2(v, 0.0f);
    }
    __syncthreads();
    fft4096_shared(sh, W, tid);
    #pragma unroll
    for (int s = 0; s < 8; s++) {
        int f = tid + s*512;
        g_Xf[(size_t)d * NFFT + f] = sh[f];
    }
}

// Forward FFT of each phi filter. One block per k. phi layout (t, k).
__global__ void __launch_bounds__(512) fft_phi_kernel(const float* __restrict__ phi) {
    __shared__ float2 sh[NFFT];
    __shared__ float2 W[NFFT/2];
    int k = blockIdx.x, tid = threadIdx.x;
    #pragma unroll
    for (int s = 0; s < 4; s++) {
        int j = tid + s*512;
        float th = -2.0f * CUDART_PI_F * (float)j / (float)NFFT;
        float sn, cs; sincosf(th, &sn, &cs);
        W[j] = make_float2(cs, sn);
    }
    #pragma unroll
    for (int s = 0; s < 8; s++) {
        int t = tid + s*512;
        float v = (t < LSEQ) ? phi[t * KF + k] : 0.0f;
        sh[t] = make_float2(v, 0.0f);
    }
    __syncthreads();
    fft4096_shared(sh, W, tid);
    #pragma unroll
    for (int s = 0; s < 8; s++) {
        int f = tid + s*512;
        g_Vf[(size_t)k * NFFT + f] = sh[f];
    }
}

// Product + packed inverse FFT per (k, d). Two real irffts per complex ifft:
//   z[f] = V[f]*(X[f] + i*X[(f+2048) mod 4096])   (plus path Re, minus path Im)
// Output: Ucat rows (t-contiguous).
__global__ void __launch_bounds__(512) conv_ifft_kernel() {
    __shared__ float2 sh[NFFT];
    __shared__ float2 W[NFFT/2];
    int b = blockIdx.x;          // b = k*DDIM + d
    int k = b / DDIM;
    int d = b - k*DDIM;
    int tid = threadIdx.x;
    #pragma unroll
    for (int s = 0; s < 4; s++) {
        int j = tid + s*512;
        float th = 2.0f * CUDART_PI_F * (float)j / (float)NFFT;  // inverse sign
        float sn, cs; sincosf(th, &sn, &cs);
        W[j] = make_float2(cs, sn);
    }
    #pragma unroll
    for (int s = 0; s < 8; s++) {
        int f = tid + s*512;
        float2 V  = g_Vf[(size_t)k * NFFT + f];
        float2 A  = g_Xf[(size_t)d * NFFT + f];
        float2 Bs = g_Xf[(size_t)d * NFFT + ((f + 2048) & (NFFT-1))];
        float2 comb = make_float2(A.x - Bs.y, A.y + Bs.x);  // A + i*Bs
        sh[f] = cmul(V, comb);
    }
    __syncthreads();
    fft4096_shared(sh, W, tid);
    const float scale = 1.0f / (float)NFFT;
    const size_t rowp = (size_t)(k*DDIM + d);
    const size_t rowm = (size_t)(KF*DDIM + k*DDIM + d);
    #pragma unroll
    for (int s = 0; s < 4; s++) {
        int t = tid + s*512;                // t < 2048
        float2 w = sh[t];
        float up = w.x * scale;
        float sg = (t & 1) ? -1.0f : 1.0f;
        float um = w.y * scale * sg;
        g_Ucat[rowp * LSEQ + t] = up;
        g_Ucat[rowm * LSEQ + t] = um;
    }
}

// Fill AR rows: Ucat[2KD + i*D + d, t] = x[t-i, d] (0 for t < i)
__global__ void arfill_kernel() {
    int idx = blockIdx.x * blockDim.x + threadIdx.x;
    if (idx >= KU * DDIM * LSEQ) return;
    int t   = idx & (LSEQ - 1);
    int rem = idx >> 11;            // LSEQ = 2048
    int d   = rem % DDIM;
    int i   = rem / DDIM;
    float v = (t >= i) ? g_xT[(size_t)d * LSEQ + t - i] : 0.0f;
    g_Ucat[(size_t)(2*KF*DDIM + i*DDIM + d) * LSEQ + t] = v;
}

// out[t, o] = sum_r Ucat[r, t] * Mcat[r, o]
// fp32 SIMT GEMM: BM=128 (t), BN=96 (o), BK=16, 256 threads, 8x6 micro-tile.
// Grid (16, 8) = 128 blocks -> one full wave on 148 SMs.
#define BM 128
#define BN 96
#define BK 16
#define TM 8
#define TN 6
__global__ void __launch_bounds__(256) gemm_kernel(float* __restrict__ out) {
    __shared__ float As[BK][BM];
    __shared__ float Bs[BK][BN];
    const int t0 = blockIdx.x * BM;
    const int o0 = blockIdx.y * BN;
    const int tid = threadIdx.x;
    const int tx = tid & 15;     // col group
    const int ty = tid >> 4;     // row group
    float acc[TM][TN];
    #pragma unroll
    for (int u = 0; u < TM; u++)
        #pragma unroll
        for (int v = 0; v < TN; v++)
            acc[u][v] = 0.0f;

    for (int r0 = 0; r0 < RTOT; r0 += BK) {
        #pragma unroll
        for (int s = 0; s < (BK*BM)/256; s++) {     // 8 loads of A
            int l  = tid + s*256;
            int kk = l >> 7;
            int m  = l & 127;
            As[kk][m] = g_Ucat[(size_t)(r0 + kk) * LSEQ + t0 + m];
        }
        #pragma unroll
        for (int s = 0; s < (BK*BN)/256; s++) {     // 6 loads of B
            int l  = tid + s*256;
            int kk = l / BN;
            int o  = l - kk*BN;
            Bs[kk][o] = g_Mcat[(size_t)(r0 + kk) * DDIM + o0 + o];
        }
        __syncthreads();
        #pragma unroll
        for (int kk = 0; kk < BK; kk++) {
            float ra[TM], rb[TN];
            #pragma unroll
            for (int u = 0; u < TM; u++) ra[u] = As[kk][ty*TM + u];
            #pragma unroll
            for (int v = 0; v < TN; v++) rb[v] = Bs[kk][tx*TN + v];
            #pragma unroll
            for (int u = 0; u < TM; u++)
                #pragma unroll
                for (int v = 0; v < TN; v++)
                    acc[u][v] += ra[u] * rb[v];
        }
        __syncthreads();
    }
    #pragma unroll
    for (int u = 0; u < TM; u++) {
        int t = t0 + ty*TM + u;
        #pragma unroll
        for (int v = 0; v < TN; v++)
            out[(size_t)t * DDIM + o0 + tx*TN + v] = acc[u][v];
    }
}

// ---------------- launch ----------------
extern "C" void kernel_launch(void* const* d_in, const int* in_sizes, int n_in,
                              void* d_out, int out_size) {
    const float* x     = (const float*)d_in[0];
    const float* phi   = (const float*)d_in[1];
    const float* sigma = (const float*)d_in[2];
    const float* Mp    = (const float*)d_in[3];
    const float* Mm    = (const float*)d_in[4];
    const float* Mu    = (const float*)d_in[5];
    float* out = (float*)d_out;

    transpose_kernel<<<dim3(LSEQ/32, DDIM/32), dim3(32, 8)>>>(x);
    mcat_kernel<<<(RTOT*DDIM + 255)/256, 256>>>(Mp, Mm, Mu, sigma);
    fft_x_kernel<<<DDIM, 512>>>();
    fft_phi_kernel<<<KF, 512>>>(phi);
    conv_ifft_kernel<<<KF*DDIM, 512>>>();
    arfill_kernel<<<(KU*DDIM*LSEQ + 255)/256, 256>>>();
    gemm_kernel<<<dim3(LSEQ/BM, DDIM/BN), 256>>>(out);
}

// round 4
// speedup vs baseline: 3.2087x; 3.2087x over previous
#include <cuda_runtime.h>
#include <cuda_fp16.h>
#include <math_constants.h>
#include <cstdint>

// Problem constants
#define LSEQ 2048
#define DDIM 768
#define KF   16
#define KU   3
#define NFFT 4096
#define RSPEC (2*KF*DDIM)            // 24576 spectral reduction rows
#define RTOT  (RSPEC + KU*DDIM)      // 26880 total reduction rows

// ---------------- device scratch (static, no allocations) ----------------
__device__ float  g_xT[DDIM*LSEQ];                 //   6 MB  x transposed (d,t)
__device__ float2 g_Xf[DDIM*NFFT];                 //  25 MB  full FFT of x per d
__device__ float2 g_Vf[KF*NFFT];                   // 0.5 MB  full FFT of phi per k
__device__ __half g_Uch[(size_t)RSPEC*LSEQ];       // 100 MB  conv results (r,t) fp16
__device__ __half g_A[(size_t)LSEQ*RTOT];          // 110 MB  GEMM A (t,r) fp16
__device__ __half g_B[(size_t)DDIM*RTOT];          //  41 MB  GEMM B (o,r) fp16

// ---------------- helpers ----------------
__device__ __forceinline__ float2 cmul(float2 a, float2 b) {
    return make_float2(a.x*b.x - a.y*b.y, a.x*b.y + a.y*b.x);
}
__device__ __forceinline__ float2 cadd(float2 a, float2 b){ return make_float2(a.x+b.x, a.y+b.y); }
__device__ __forceinline__ float2 csub(float2 a, float2 b){ return make_float2(a.x-b.x, a.y-b.y); }
__device__ __forceinline__ uint32_t s2u(const void* p) {
    uint32_t a;
    asm("{ .reg .u64 t; cvta.to.shared.u64 t, %1; cvt.u32.u64 %0, t; }" : "=r"(a) : "l"(p));
    return a;
}

// ---------------- radix-4 shared-memory 4096-pt complex FFT ----------------
__device__ __forceinline__ int digrev4096(int i) {
    int b = (int)(__brev((unsigned)i) >> 20);            // 12-bit bit reverse
    return ((b >> 1) & 0x555) | ((b & 0x555) << 1);      // swap bit pairs -> base-4 digit reverse
}

// SIGN = -1 forward, +1 inverse (unscaled)
template<int SIGN>
__device__ __forceinline__ void fft4096_r4(float2* sh, int tid) {
    #pragma unroll
    for (int s = 0; s < 8; s++) {
        int i = tid + s*512;
        int j = digrev4096(i);
        if (j > i) { float2 a = sh[i]; sh[i] = sh[j]; sh[j] = a; }
    }
    __syncthreads();
    #pragma unroll
    for (int st = 0; st < 6; st++) {
        const int q = 1 << (2*st);
        const float step = (float)SIGN * 6.28318530717958647692f / (float)(4*q);
        #pragma unroll
        for (int s = 0; s < 2; s++) {
            int b   = tid + s*512;               // butterfly id in [0,1024)
            int pos = b & (q - 1);
            int blk = b >> (2*st);
            int i0  = blk*4*q + pos;
            float2 x0 = sh[i0], x1 = sh[i0+q], x2 = sh[i0+2*q], x3 = sh[i0+3*q];
            float ang = step * (float)pos;
            float sn, cs; __sincosf(ang, &sn, &cs);
            float2 w1 = make_float2(cs, sn);
            float2 w2 = cmul(w1, w1);
            float2 w3 = cmul(w2, w1);
            x1 = cmul(x1, w1); x2 = cmul(x2, w2); x3 = cmul(x3, w3);
            float2 t0 = cadd(x0, x2), t1 = csub(x0, x2);
            float2 t2 = cadd(x1, x3), t3 = csub(x1, x3);
            float2 r3 = (SIGN < 0) ? make_float2(t3.y, -t3.x)   // -i * t3
                                   : make_float2(-t3.y, t3.x);  // +i * t3
            sh[i0]       = cadd(t0, t2);
            sh[i0 + q]   = cadd(t1, r3);
            sh[i0 + 2*q] = csub(t0, t2);
            sh[i0 + 3*q] = csub(t1, r3);
        }
        __syncthreads();
    }
}

// ---------------- kernels ----------------

// x (t, d) -> g_xT (d, t)
__global__ void transpose_kernel(const float* __restrict__ x) {
    __shared__ float tile[32][33];
    int t0 = blockIdx.x * 32;
    int d0 = blockIdx.y * 32;
    int tx = threadIdx.x, ty = threadIdx.y;   // block (32, 8)
    #pragma unroll
    for (int s = 0; s < 32; s += 8)
        tile[ty + s][tx] = x[(t0 + ty + s) * DDIM + d0 + tx];
    __syncthreads();
    #pragma unroll
    for (int s = 0; s < 32; s += 8)
        g_xT[(size_t)(d0 + ty + s) * LSEQ + t0 + tx] = tile[tx][ty + s];
}

// Forward FFT of each x channel (zero-padded to 4096). One block per d.
__global__ void __launch_bounds__(512) fft_x_kernel() {
    __shared__ float2 sh[NFFT];
    int d = blockIdx.x, tid = threadIdx.x;
    #pragma unroll
    for (int s = 0; s < 8; s++) {
        int t = tid + s*512;
        float v = (t < LSEQ) ? g_xT[(size_t)d * LSEQ + t] : 0.0f;
        sh[t] = make_float2(v, 0.0f);
    }
    __syncthreads();
    fft4096_r4<-1>(sh, tid);
    #pragma unroll
    for (int s = 0; s < 8; s++) {
        int f = tid + s*512;
        g_Xf[(size_t)d * NFFT + f] = sh[f];
    }
}

// Forward FFT of each phi filter. One block per k. phi layout (t, k).
__global__ void __launch_bounds__(512) fft_phi_kernel(const float* __restrict__ phi) {
    __shared__ float2 sh[NFFT];
    int k = blockIdx.x, tid = threadIdx.x;
    #pragma unroll
    for (int s = 0; s < 8; s++) {
        int t = tid + s*512;
        float v = (t < LSEQ) ? phi[t * KF + k] : 0.0f;
        sh[t] = make_float2(v, 0.0f);
    }
    __syncthreads();
    fft4096_r4<-1>(sh, tid);
    #pragma unroll
    for (int s = 0; s < 8; s++) {
        int f = tid + s*512;
        g_Vf[(size_t)k * NFFT + f] = sh[f];
    }
}

// Product + packed inverse FFT per (k, d): z = V*(X + i*Xshift); Re->plus, Im->minus.
// Writes fp16 (r, t) rows.
__global__ void __launch_bounds__(512) conv_ifft_kernel() {
    __shared__ float2 sh[NFFT];
    int b = blockIdx.x;          // b = k*DDIM + d
    int k = b / DDIM;
    int d = b - k*DDIM;
    int tid = threadIdx.x;
    #pragma unroll
    for (int s = 0; s < 8; s++) {
        int f = tid + s*512;
        float2 V  = g_Vf[(size_t)k * NFFT + f];
        float2 A  = g_Xf[(size_t)d * NFFT + f];
        float2 Bs = g_Xf[(size_t)d * NFFT + ((f + 2048) & (NFFT-1))];
        float2 comb = make_float2(A.x - Bs.y, A.y + Bs.x);  // A + i*Bs
        sh[f] = cmul(V, comb);
    }
    __syncthreads();
    fft4096_r4<1>(sh, tid);
    const float scale = 1.0f / (float)NFFT;
    const size_t rowp = (size_t)(k*DDIM + d);
    const size_t rowm = (size_t)(KF*DDIM + k*DDIM + d);
    #pragma unroll
    for (int s = 0; s < 4; s++) {
        int t = tid + s*512;
        float2 w = sh[t];
        float up = w.x * scale;
        float sg = (t & 1) ? -1.0f : 1.0f;
        float um = w.y * scale * sg;
        g_Uch[rowp * LSEQ + t] = __float2half_rn(up);
        g_Uch[rowm * LSEQ + t] = __float2half_rn(um);
    }
}

// Transpose fp16: g_Uch (r,t) -> g_A (t,r)
__global__ void ucatT_kernel() {
    __shared__ __half tile[32][33];
    int r0 = blockIdx.x * 32;
    int t0 = blockIdx.y * 32;
    int tx = threadIdx.x, ty = threadIdx.y;   // block (32, 8)
    #pragma unroll
    for (int s = 0; s < 32; s += 8)
        tile[ty + s][tx] = g_Uch[(size_t)(r0 + ty + s) * LSEQ + t0 + tx];
    __syncthreads();
    #pragma unroll
    for (int s = 0; s < 32; s += 8)
        g_A[(size_t)(t0 + ty + s) * RTOT + r0 + tx] = tile[tx][ty + s];
}

// AR rows of A: A[t][RSPEC + i*DDIM + d] = x[t-i][d]
__global__ void arfill_kernel(const float* __restrict__ x) {
    int idx = blockIdx.x * blockDim.x + threadIdx.x;
    if (idx >= LSEQ * KU * DDIM) return;
    int t   = idx / (KU * DDIM);
    int rem = idx - t * (KU * DDIM);
    int i   = rem / DDIM;
    int d   = rem - i * DDIM;
    float v = (t >= i) ? x[(size_t)(t - i) * DDIM + d] : 0.0f;
    g_A[(size_t)t * RTOT + RSPEC + (size_t)i * DDIM + d] = __float2half_rn(v);
}

// Build B = Mcat^T in fp16: B[o][r], r contiguous. Scaled by sigma^(1/4).
__global__ void mcatT_kernel(const float* __restrict__ Mp,
                             const float* __restrict__ Mm,
                             const float* __restrict__ Mu,
                             const float* __restrict__ sigma) {
    __shared__ float tile[32][33];
    int r0 = blockIdx.x * 32;
    int o0 = blockIdx.y * 32;
    int tx = threadIdx.x, ty = threadIdx.y;   // block (32, 8)
    #pragma unroll
    for (int s = 0; s < 32; s += 8) {
        int r = r0 + ty + s;
        int o = o0 + tx;
        float v;
        if (r < KF*DDIM) {
            float s4 = sqrtf(sqrtf(sigma[r / DDIM]));
            v = Mp[(size_t)r * DDIM + o] * s4;
        } else if (r < RSPEC) {
            int rr = r - KF*DDIM;
            float s4 = sqrtf(sqrtf(sigma[rr / DDIM]));
            v = Mm[(size_t)rr * DDIM + o] * s4;
        } else {
            v = Mu[(size_t)(r - RSPEC) * DDIM + o];
        }
        tile[ty + s][tx] = v;
    }
    __syncthreads();
    #pragma unroll
    for (int s = 0; s < 32; s += 8)
        g_B[(size_t)(o0 + ty + s) * RTOT + r0 + tx] = __float2half_rn(tile[tx][ty + s]);
}

// ---------------- fp16 mma.sync GEMM ----------------
// out[t,o] = sum_r A[t,r] * B[o,r].  BM=128, BN=96, BK=32. 256 threads (8 warps, 2x4).
#define BM 128
#define BN 96
#define BK 32
#define NK (RTOT/BK)            // 840
#define ASTRIDE 80              // bytes per smem row: 64B data + 16B pad (bank-conflict-free)
#define ATILEB (BM*ASTRIDE)     // 10240
#define BTILEB (BN*ASTRIDE)     // 7680
#define STAGEB (ATILEB + BTILEB)

__device__ __forceinline__ void cp16(uint32_t dst, const void* src) {
    asm volatile("cp.async.cg.shared.global [%0], [%1], 16;" :: "r"(dst), "l"(src));
}
#define LDSM4(R, addr) \
    asm volatile("ldmatrix.sync.aligned.m8n8.x4.shared.b16 {%0,%1,%2,%3}, [%4];" \
        : "=r"((R)[0]), "=r"((R)[1]), "=r"((R)[2]), "=r"((R)[3]) : "r"(addr))
#define LDSM2(R, addr) \
    asm volatile("ldmatrix.sync.aligned.m8n8.x2.shared.b16 {%0,%1}, [%2];" \
        : "=r"((R)[0]), "=r"((R)[1]) : "r"(addr))
#define MMA16816(C, A, B) \
    asm volatile("mma.sync.aligned.m16n8k16.row.col.f32.f16.f16.f32 " \
        "{%0,%1,%2,%3}, {%4,%5,%6,%7}, {%8,%9}, {%0,%1,%2,%3};" \
        : "+f"((C)[0]), "+f"((C)[1]), "+f"((C)[2]), "+f"((C)[3]) \
        : "r"((A)[0]), "r"((A)[1]), "r"((A)[2]), "r"((A)[3]), "r"((B)[0]), "r"((B)[1]))

__global__ void __launch_bounds__(256, 1) gemm_kernel(float* __restrict__ out) {
    __shared__ __align__(16) char sm[2*STAGEB];
    const int tid  = threadIdx.x;
    const int lane = tid & 31;
    const int wid  = tid >> 5;
    const int wm   = wid >> 2;     // 0..1  (m 64 each)
    const int wn   = wid & 3;      // 0..3  (n 24 each)
    const int t0   = blockIdx.x * BM;
    const int o0   = blockIdx.y * BN;
    const uint32_t sbase = s2u(sm);

    // ---- cp.async source/dest assignments (fixed per thread) ----
    // A: 512 chunks of 16B: id = c*128 + row  (c = k-chunk 0..3, row 0..127)
    const int aid0 = tid,      ac0 = aid0 >> 7, ar0 = aid0 & 127;
    const int aid1 = tid + 256, ac1 = aid1 >> 7, ar1 = aid1 & 127;
    const __half* pA0 = g_A + (size_t)(t0 + ar0) * RTOT + ac0*8;
    const __half* pA1 = g_A + (size_t)(t0 + ar1) * RTOT + ac1*8;
    const uint32_t dA0 = (uint32_t)(ar0*ASTRIDE + ac0*16);
    const uint32_t dA1 = (uint32_t)(ar1*ASTRIDE + ac1*16);
    // B: 384 chunks: id -> c = id/96, row = id%96
    const int bid0 = tid,       bc0 = bid0 / 96, br0 = bid0 - 96*bc0;
    const __half* pB0 = g_B + (size_t)(o0 + br0) * RTOT + bc0*8;
    const uint32_t dB0 = (uint32_t)(br0*ASTRIDE + bc0*16);
    const bool hasB1 = (tid < 128);
    const int bid1 = tid + 256, bc1 = bid1 / 96, br1 = bid1 - 96*bc1;
    const __half* pB1 = g_B + (size_t)(o0 + br1) * RTOT + bc1*8;
    const uint32_t dB1 = (uint32_t)(br1*ASTRIDE + bc1*16);

    // ---- ldmatrix lane-dependent offsets ----
    const int lrA = lane & 15;          // row within m16 tile
    const int lcA = lane >> 4;          // k-chunk select (0/1)
    const int grp = lane >> 3;
    const int rB01 = ((grp >> 1) << 3) + (lane & 7);   // tile(0/1)*8 + row
    const int cB01 = grp & 1;
    const int rB2  = 16 + (lane & 7);
    const int cB2  = (lane >> 3) & 1;

    float acc[4][3][4];
    #pragma unroll
    for (int mi = 0; mi < 4; mi++)
        #pragma unroll
        for (int ni = 0; ni < 3; ni++)
            #pragma unroll
            for (int e = 0; e < 4; e++) acc[mi][ni][e] = 0.0f;

    // prologue: stage 0
    {
        uint32_t s = sbase;
        cp16(s + dA0, pA0); cp16(s + dA1, pA1);
        uint32_t sB = s + ATILEB;
        cp16(sB + dB0, pB0);
        if (hasB1) cp16(sB + dB1, pB1);
        asm volatile("cp.async.commit_group;");
    }

    #pragma unroll 1
    for (int c = 0; c < NK; c++) {
        const int buf = c & 1;
        if (c + 1 < NK) {
            size_t off = (size_t)(c + 1) * BK;
            uint32_t s = sbase + (buf ^ 1)*STAGEB;
            cp16(s + dA0, pA0 + off); cp16(s + dA1, pA1 + off);
            uint32_t sB = s + ATILEB;
            cp16(sB + dB0, pB0 + off);
            if (hasB1) cp16(sB + dB1, pB1 + off);
            asm volatile("cp.async.commit_group;");
            asm volatile("cp.async.wait_group %0;" :: "n"(1));
        } else {
            asm volatile("cp.async.wait_group %0;" :: "n"(0));
        }
        __syncthreads();

        const uint32_t sA = sbase + buf*STAGEB;
        const uint32_t sB = sA + ATILEB;
        #pragma unroll
        for (int j = 0; j < 2; j++) {
            uint32_t a[4][4];
            #pragma unroll
            for (int mi = 0; mi < 4; mi++) {
                uint32_t addr = sA + (uint32_t)((wm*64 + mi*16 + lrA)*ASTRIDE + (2*j + lcA)*16);
                LDSM4(a[mi], addr);
            }
            uint32_t b[3][2];
            {
                uint32_t addr = sB + (uint32_t)((wn*24 + rB01)*ASTRIDE + (2*j + cB01)*16);
                uint32_t r4[4]; LDSM4(r4, addr);
                b[0][0] = r4[0]; b[0][1] = r4[1];
                b[1][0] = r4[2]; b[1][1] = r4[3];
                uint32_t addr2 = sB + (uint32_t)((wn*24 + rB2)*ASTRIDE + (2*j + cB2)*16);
                LDSM2(b[2], addr2);
            }
            #pragma unroll
            for (int mi = 0; mi < 4; mi++)
                #pragma unroll
                for (int ni = 0; ni < 3; ni++)
                    MMA16816(acc[mi][ni], a[mi], b[ni]);
        }
        __syncthreads();
    }

    // epilogue
    const int row  = lane >> 2;
    const int col2 = (lane & 3) * 2;
    #pragma unroll
    for (int mi = 0; mi < 4; mi++) {
        #pragma unroll
        for (int ni = 0; ni < 3; ni++) {
            int t = t0 + wm*64 + mi*16 + row;
            int o = o0 + wn*24 + ni*8 + col2;
            float* p0 = out + (size_t)t * DDIM + o;
            float* p1 = out + (size_t)(t + 8) * DDIM + o;
            p0[0] = acc[mi][ni][0]; p0[1] = acc[mi][ni][1];
            p1[0] = acc[mi][ni][2]; p1[1] = acc[mi][ni][3];
        }
    }
}

// ---------------- launch ----------------
extern "C" void kernel_launch(void* const* d_in, const int* in_sizes, int n_in,
                              void* d_out, int out_size) {
    const float* x     = (const float*)d_in[0];
    const float* phi   = (const float*)d_in[1];
    const float* sigma = (const float*)d_in[2];
    const float* Mp    = (const float*)d_in[3];
    const float* Mm    = (const float*)d_in[4];
    const float* Mu    = (const float*)d_in[5];
    float* out = (float*)d_out;

    transpose_kernel<<<dim3(LSEQ/32, DDIM/32), dim3(32, 8)>>>(x);
    fft_x_kernel<<<DDIM, 512>>>();
    fft_phi_kernel<<<KF, 512>>>(phi);
    conv_ifft_kernel<<<KF*DDIM, 512>>>();
    ucatT_kernel<<<dim3(RSPEC/32, LSEQ/32), dim3(32, 8)>>>();
    arfill_kernel<<<(LSEQ*KU*DDIM + 255)/256, 256>>>(x);
    mcatT_kernel<<<dim3(RTOT/32, DDIM/32), dim3(32, 8)>>>(Mp, Mm, Mu, sigma);
    gemm_kernel<<<dim3(LSEQ/BM, DDIM/BN), 256>>>(out);
}

// round 5
// speedup vs baseline: 3.2123x; 1.0011x over previous
#include <cuda_runtime.h>
#include <cuda_fp16.h>
#include <math_constants.h>
#include <cstdint>

// Problem constants
#define LSEQ 2048
#define DDIM 768
#define KF   16
#define KU   3
#define NFFT 4096
#define RSPEC (2*KF*DDIM)            // 24576 spectral reduction rows
#define RTOT  (RSPEC + KU*DDIM)      // 26880 total reduction rows

// ---------------- device scratch (static, no allocations) ----------------
__device__ float  g_xT[DDIM*LSEQ];                 //   6 MB  x transposed (d,t)
__device__ float2 g_Xf[DDIM*NFFT];                 //  25 MB  full FFT of x per d
__device__ float2 g_Vf[KF*NFFT];                   // 0.5 MB  full FFT of phi per k
__device__ __half g_Uch[(size_t)RSPEC*LSEQ];       // 100 MB  conv results (r,t) fp16
__device__ __half g_A[(size_t)LSEQ*RTOT];          // 110 MB  GEMM A (t,r) fp16
__device__ __half g_B[(size_t)DDIM*RTOT];          //  41 MB  GEMM B (o,r) fp16

// ---------------- helpers ----------------
__device__ __forceinline__ float2 cmul(float2 a, float2 b) {
    return make_float2(a.x*b.x - a.y*b.y, a.x*b.y + a.y*b.x);
}
__device__ __forceinline__ float2 cadd(float2 a, float2 b){ return make_float2(a.x+b.x, a.y+b.y); }
__device__ __forceinline__ float2 csub(float2 a, float2 b){ return make_float2(a.x-b.x, a.y-b.y); }
__device__ __forceinline__ uint32_t s2u(const void* p) {
    uint32_t a;
    asm("{ .reg .u64 t; cvta.to.shared.u64 t, %1; cvt.u32.u64 %0, t; }" : "=r"(a) : "l"(p));
    return a;
}

// ---------------- radix-4 shared-memory 4096-pt complex FFT ----------------
__device__ __forceinline__ int digrev4096(int i) {
    int b = (int)(__brev((unsigned)i) >> 20);            // 12-bit bit reverse
    return ((b >> 1) & 0x555) | ((b & 0x555) << 1);      // swap bit pairs -> base-4 digit reverse
}

// SIGN = -1 forward, +1 inverse (unscaled)
template<int SIGN>
__device__ __forceinline__ void fft4096_r4(float2* sh, int tid) {
    #pragma unroll
    for (int s = 0; s < 8; s++) {
        int i = tid + s*512;
        int j = digrev4096(i);
        if (j > i) { float2 a = sh[i]; sh[i] = sh[j]; sh[j] = a; }
    }
    __syncthreads();
    #pragma unroll
    for (int st = 0; st < 6; st++) {
        const int q = 1 << (2*st);
        const float step = (float)SIGN * 6.28318530717958647692f / (float)(4*q);
        #pragma unroll
        for (int s = 0; s < 2; s++) {
            int b   = tid + s*512;               // butterfly id in [0,1024)
            int pos = b & (q - 1);
            int blk = b >> (2*st);
            int i0  = blk*4*q + pos;
            float2 x0 = sh[i0], x1 = sh[i0+q], x2 = sh[i0+2*q], x3 = sh[i0+3*q];
            float ang = step * (float)pos;
            float sn, cs; __sincosf(ang, &sn, &cs);
            float2 w1 = make_float2(cs, sn);
            float2 w2 = cmul(w1, w1);
            float2 w3 = cmul(w2, w1);
            x1 = cmul(x1, w1); x2 = cmul(x2, w2); x3 = cmul(x3, w3);
            float2 t0 = cadd(x0, x2), t1 = csub(x0, x2);
            float2 t2 = cadd(x1, x3), t3 = csub(x1, x3);
            float2 r3 = (SIGN < 0) ? make_float2(t3.y, -t3.x)   // -i * t3
                                   : make_float2(-t3.y, t3.x);  // +i * t3
            sh[i0]       = cadd(t0, t2);
            sh[i0 + q]   = cadd(t1, r3);
            sh[i0 + 2*q] = csub(t0, t2);
            sh[i0 + 3*q] = csub(t1, r3);
        }
        __syncthreads();
    }
}

// ---------------- kernels ----------------

// x (t, d) -> g_xT (d, t)
__global__ void transpose_kernel(const float* __restrict__ x) {
    __shared__ float tile[32][33];
    int t0 = blockIdx.x * 32;
    int d0 = blockIdx.y * 32;
    int tx = threadIdx.x, ty = threadIdx.y;   // block (32, 8)
    #pragma unroll
    for (int s = 0; s < 32; s += 8)
        tile[ty + s][tx] = x[(t0 + ty + s) * DDIM + d0 + tx];
    __syncthreads();
    #pragma unroll
    for (int s = 0; s < 32; s += 8)
        g_xT[(size_t)(d0 + ty + s) * LSEQ + t0 + tx] = tile[tx][ty + s];
}

// Forward FFT of each x channel (zero-padded to 4096). One block per d.
__global__ void __launch_bounds__(512) fft_x_kernel() {
    __shared__ float2 sh[NFFT];
    int d = blockIdx.x, tid = threadIdx.x;
    #pragma unroll
    for (int s = 0; s < 8; s++) {
        int t = tid + s*512;
        float v = (t < LSEQ) ? g_xT[(size_t)d * LSEQ + t] : 0.0f;
        sh[t] = make_float2(v, 0.0f);
    }
    __syncthreads();
    fft4096_r4<-1>(sh, tid);
    #pragma unroll
    for (int s = 0; s < 8; s++) {
        int f = tid + s*512;
        g_Xf[(size_t)d * NFFT + f] = sh[f];
    }
}

// Forward FFT of each phi filter. One block per k. phi layout (t, k).
__global__ void __launch_bounds__(512) fft_phi_kernel(const float* __restrict__ phi) {
    __shared__ float2 sh[NFFT];
    int k = blockIdx.x, tid = threadIdx.x;
    #pragma unroll
    for (int s = 0; s < 8; s++) {
        int t = tid + s*512;
        float v = (t < LSEQ) ? phi[t * KF + k] : 0.0f;
        sh[t] = make_float2(v, 0.0f);
    }
    __syncthreads();
    fft4096_r4<-1>(sh, tid);
    #pragma unroll
    for (int s = 0; s < 8; s++) {
        int f = tid + s*512;
        g_Vf[(size_t)k * NFFT + f] = sh[f];
    }
}

// Product + packed inverse FFT per (k, d): z = V*(X + i*Xshift); Re->plus, Im->minus.
// Writes fp16 (r, t) rows.
__global__ void __launch_bounds__(512) conv_ifft_kernel() {
    __shared__ float2 sh[NFFT];
    int b = blockIdx.x;          // b = k*DDIM + d
    int k = b / DDIM;
    int d = b - k*DDIM;
    int tid = threadIdx.x;
    #pragma unroll
    for (int s = 0; s < 8; s++) {
        int f = tid + s*512;
        float2 V  = g_Vf[(size_t)k * NFFT + f];
        float2 A  = g_Xf[(size_t)d * NFFT + f];
        float2 Bs = g_Xf[(size_t)d * NFFT + ((f + 2048) & (NFFT-1))];
        float2 comb = make_float2(A.x - Bs.y, A.y + Bs.x);  // A + i*Bs
        sh[f] = cmul(V, comb);
    }
    __syncthreads();
    fft4096_r4<1>(sh, tid);
    const float scale = 1.0f / (float)NFFT;
    const size_t rowp = (size_t)(k*DDIM + d);
    const size_t rowm = (size_t)(KF*DDIM + k*DDIM + d);
    #pragma unroll
    for (int s = 0; s < 4; s++) {
        int t = tid + s*512;
        float2 w = sh[t];
        float up = w.x * scale;
        float sg = (t & 1) ? -1.0f : 1.0f;
        float um = w.y * scale * sg;
        g_Uch[rowp * LSEQ + t] = __float2half_rn(up);
        g_Uch[rowm * LSEQ + t] = __float2half_rn(um);
    }
}

// Transpose fp16: g_Uch (r,t) -> g_A (t,r)
__global__ void ucatT_kernel() {
    __shared__ __half tile[32][33];
    int r0 = blockIdx.x * 32;
    int t0 = blockIdx.y * 32;
    int tx = threadIdx.x, ty = threadIdx.y;   // block (32, 8)
    #pragma unroll
    for (int s = 0; s < 32; s += 8)
        tile[ty + s][tx] = g_Uch[(size_t)(r0 + ty + s) * LSEQ + t0 + tx];
    __syncthreads();
    #pragma unroll
    for (int s = 0; s < 32; s += 8)
        g_A[(size_t)(t0 + ty + s) * RTOT + r0 + tx] = tile[tx][ty + s];
}

// AR rows of A: A[t][RSPEC + i*DDIM + d] = x[t-i][d]
__global__ void arfill_kernel(const float* __restrict__ x) {
    int idx = blockIdx.x * blockDim.x + threadIdx.x;
    if (idx >= LSEQ * KU * DDIM) return;
    int t   = idx / (KU * DDIM);
    int rem = idx - t * (KU * DDIM);
    int i   = rem / DDIM;
    int d   = rem - i * DDIM;
    float v = (t >= i) ? x[(size_t)(t - i) * DDIM + d] : 0.0f;
    g_A[(size_t)t * RTOT + RSPEC + (size_t)i * DDIM + d] = __float2half_rn(v);
}

// Build B = Mcat^T in fp16: B[o][r], r contiguous. Scaled by sigma^(1/4).
__global__ void mcatT_kernel(const float* __restrict__ Mp,
                             const float* __restrict__ Mm,
                             const float* __restrict__ Mu,
                             const float* __restrict__ sigma) {
    __shared__ float tile[32][33];
    int r0 = blockIdx.x * 32;
    int o0 = blockIdx.y * 32;
    int tx = threadIdx.x, ty = threadIdx.y;   // block (32, 8)
    #pragma unroll
    for (int s = 0; s < 32; s += 8) {
        int r = r0 + ty + s;
        int o = o0 + tx;
        float v;
        if (r < KF*DDIM) {
            float s4 = sqrtf(sqrtf(sigma[r / DDIM]));
            v = Mp[(size_t)r * DDIM + o] * s4;
        } else if (r < RSPEC) {
            int rr = r - KF*DDIM;
            float s4 = sqrtf(sqrtf(sigma[rr / DDIM]));
            v = Mm[(size_t)rr * DDIM + o] * s4;
        } else {
            v = Mu[(size_t)(r - RSPEC) * DDIM + o];
        }
        tile[ty + s][tx] = v;
    }
    __syncthreads();
    #pragma unroll
    for (int s = 0; s < 32; s += 8)
        g_B[(size_t)(o0 + ty + s) * RTOT + r0 + tx] = __float2half_rn(tile[tx][ty + s]);
}

// ---------------- fp16 mma.sync GEMM ----------------
// out[t,o] = sum_r A[t,r] * B[o,r].  BM=128, BN=96, BK=32. 256 threads (8 warps, 2x4).
#define BM 128
#define BN 96
#define BK 32
#define NK (RTOT/BK)            // 840
#define ASTRIDE 80              // bytes per smem row: 64B data + 16B pad (bank-conflict-free)
#define ATILEB (BM*ASTRIDE)     // 10240
#define BTILEB (BN*ASTRIDE)     // 7680
#define STAGEB (ATILEB + BTILEB)

__device__ __forceinline__ void cp16(uint32_t dst, const void* src) {
    asm volatile("cp.async.cg.shared.global [%0], [%1], 16;" :: "r"(dst), "l"(src));
}
#define LDSM4(R, addr) \
    asm volatile("ldmatrix.sync.aligned.m8n8.x4.shared.b16 {%0,%1,%2,%3}, [%4];" \
        : "=r"((R)[0]), "=r"((R)[1]), "=r"((R)[2]), "=r"((R)[3]) : "r"(addr))
#define LDSM2(R, addr) \
    asm volatile("ldmatrix.sync.aligned.m8n8.x2.shared.b16 {%0,%1}, [%2];" \
        : "=r"((R)[0]), "=r"((R)[1]) : "r"(addr))
#define MMA16816(C, A, B) \
    asm volatile("mma.sync.aligned.m16n8k16.row.col.f32.f16.f16.f32 " \
        "{%0,%1,%2,%3}, {%4,%5,%6,%7}, {%8,%9}, {%0,%1,%2,%3};" \
        : "+f"((C)[0]), "+f"((C)[1]), "+f"((C)[2]), "+f"((C)[3]) \
        : "r"((A)[0]), "r"((A)[1]), "r"((A)[2]), "r"((A)[3]), "r"((B)[0]), "r"((B)[1]))

__global__ void __launch_bounds__(256, 1) gemm_kernel(float* __restrict__ out) {
    __shared__ __align__(16) char sm[2*STAGEB];
    const int tid  = threadIdx.x;
    const int lane = tid & 31;
    const int wid  = tid >> 5;
    const int wm   = wid >> 2;     // 0..1  (m 64 each)
    const int wn   = wid & 3;      // 0..3  (n 24 each)
    const int t0   = blockIdx.x * BM;
    const int o0   = blockIdx.y * BN;
    const uint32_t sbase = s2u(sm);

    // ---- cp.async source/dest assignments (fixed per thread) ----
    // A: 512 chunks of 16B: id = c*128 + row  (c = k-chunk 0..3, row 0..127)
    const int aid0 = tid,      ac0 = aid0 >> 7, ar0 = aid0 & 127;
    const int aid1 = tid + 256, ac1 = aid1 >> 7, ar1 = aid1 & 127;
    const __half* pA0 = g_A + (size_t)(t0 + ar0) * RTOT + ac0*8;
    const __half* pA1 = g_A + (size_t)(t0 + ar1) * RTOT + ac1*8;
    const uint32_t dA0 = (uint32_t)(ar0*ASTRIDE + ac0*16);
    const uint32_t dA1 = (uint32_t)(ar1*ASTRIDE + ac1*16);
    // B: 384 chunks: id -> c = id/96, row = id%96
    const int bid0 = tid,       bc0 = bid0 / 96, br0 = bid0 - 96*bc0;
    const __half* pB0 = g_B + (size_t)(o0 + br0) * RTOT + bc0*8;
    const uint32_t dB0 = (uint32_t)(br0*ASTRIDE + bc0*16);
    const bool hasB1 = (tid < 128);
    const int bid1 = tid + 256, bc1 = bid1 / 96, br1 = bid1 - 96*bc1;
    const __half* pB1 = g_B + (size_t)(o0 + br1) * RTOT + bc1*8;
    const uint32_t dB1 = (uint32_t)(br1*ASTRIDE + bc1*16);

    // ---- ldmatrix lane-dependent offsets ----
    const int lrA = lane & 15;          // row within m16 tile
    const int lcA = lane >> 4;          // k-chunk select (0/1)
    const int grp = lane >> 3;
    const int rB01 = ((grp >> 1) << 3) + (lane & 7);   // tile(0/1)*8 + row
    const int cB01 = grp & 1;
    const int rB2  = 16 + (lane & 7);
    const int cB2  = (lane >> 3) & 1;

    float acc[4][3][4];
    #pragma unroll
    for (int mi = 0; mi < 4; mi++)
        #pragma unroll
        for (int ni = 0; ni < 3; ni++)
            #pragma unroll
            for (int e = 0; e < 4; e++) acc[mi][ni][e] = 0.0f;

    // prologue: stage 0
    {
        uint32_t s = sbase;
        cp16(s + dA0, pA0); cp16(s + dA1, pA1);
        uint32_t sB = s + ATILEB;
        cp16(sB + dB0, pB0);
        if (hasB1) cp16(sB + dB1, pB1);
        asm volatile("cp.async.commit_group;");
    }

    #pragma unroll 1
    for (int c = 0; c < NK; c++) {
        const int buf = c & 1;
        if (c + 1 < NK) {
            size_t off = (size_t)(c + 1) * BK;
            uint32_t s = sbase + (buf ^ 1)*STAGEB;
            cp16(s + dA0, pA0 + off); cp16(s + dA1, pA1 + off);
            uint32_t sB = s + ATILEB;
            cp16(sB + dB0, pB0 + off);
            if (hasB1) cp16(sB + dB1, pB1 + off);
            asm volatile("cp.async.commit_group;");
            asm volatile("cp.async.wait_group %0;" :: "n"(1));
        } else {
            asm volatile("cp.async.wait_group %0;" :: "n"(0));
        }
        __syncthreads();

        const uint32_t sA = sbase + buf*STAGEB;
        const uint32_t sB = sA + ATILEB;
        #pragma unroll
        for (int j = 0; j < 2; j++) {
            uint32_t a[4][4];
            #pragma unroll
            for (int mi = 0; mi < 4; mi++) {
                uint32_t addr = sA + (uint32_t)((wm*64 + mi*16 + lrA)*ASTRIDE + (2*j + lcA)*16);
                LDSM4(a[mi], addr);
            }
            uint32_t b[3][2];
            {
                uint32_t addr = sB + (uint32_t)((wn*24 + rB01)*ASTRIDE + (2*j + cB01)*16);
                uint32_t r4[4]; LDSM4(r4, addr);
                b[0][0] = r4[0]; b[0][1] = r4[1];
                b[1][0] = r4[2]; b[1][1] = r4[3];
                uint32_t addr2 = sB + (uint32_t)((wn*24 + rB2)*ASTRIDE + (2*j + cB2)*16);
                LDSM2(b[2], addr2);
            }
            #pragma unroll
            for (int mi = 0; mi < 4; mi++)
                #pragma unroll
                for (int ni = 0; ni < 3; ni++)
                    MMA16816(acc[mi][ni], a[mi], b[ni]);
        }
        __syncthreads();
    }

    // epilogue
    const int row  = lane >> 2;
    const int col2 = (lane & 3) * 2;
    #pragma unroll
    for (int mi = 0; mi < 4; mi++) {
        #pragma unroll
        for (int ni = 0; ni < 3; ni++) {
            int t = t0 + wm*64 + mi*16 + row;
            int o = o0 + wn*24 + ni*8 + col2;
            float* p0 = out + (size_t)t * DDIM + o;
            float* p1 = out + (size_t)(t + 8) * DDIM + o;
            p0[0] = acc[mi][ni][0]; p0[1] = acc[mi][ni][1];
            p1[0] = acc[mi][ni][2]; p1[1] = acc[mi][ni][3];
        }
    }
}

// ---------------- launch ----------------
extern "C" void kernel_launch(void* const* d_in, const int* in_sizes, int n_in,
                              void* d_out, int out_size) {
    const float* x     = (const float*)d_in[0];
    const float* phi   = (const float*)d_in[1];
    const float* sigma = (const float*)d_in[2];
    const float* Mp    = (const float*)d_in[3];
    const float* Mm    = (const float*)d_in[4];
    const float* Mu    = (const float*)d_in[5];
    float* out = (float*)d_out;

    transpose_kernel<<<dim3(LSEQ/32, DDIM/32), dim3(32, 8)>>>(x);
    fft_x_kernel<<<DDIM, 512>>>();
    fft_phi_kernel<<<KF, 512>>>(phi);
    conv_ifft_kernel<<<KF*DDIM, 512>>>();
    ucatT_kernel<<<dim3(RSPEC/32, LSEQ/32), dim3(32, 8)>>>();
    arfill_kernel<<<(LSEQ*KU*DDIM + 255)/256, 256>>>(x);
    mcatT_kernel<<<dim3(RTOT/32, DDIM/32), dim3(32, 8)>>>(Mp, Mm, Mu, sigma);
    gemm_kernel<<<dim3(LSEQ/BM, DDIM/BN), 256>>>(out);
}

// round 6
// speedup vs baseline: 4.8362x; 1.5055x over previous
#include <cuda_runtime.h>
#include <cuda_fp16.h>
#include <math_constants.h>
#include <cstdint>

#define LSEQ 2048
#define DDIM 768
#define KF   16
#define KU   3
#define NFFT 4096
#define RSPEC (2*KF*DDIM)            // 24576
#define RTOT  (RSPEC + KU*DDIM)      // 26880
#define TWO_PI 6.283185307179586476925f

// ---------------- device scratch ----------------
__device__ float  g_xT[DDIM*LSEQ];
__device__ float2 g_Xf[DDIM*NFFT];            // digit-reversed spectra of x
__device__ float2 g_Vf[KF*NFFT];              // digit-reversed spectra of phi, pre-scaled 1/N
__device__ __half g_Uch[(size_t)RSPEC*LSEQ];  // conv results (r,t)
__device__ __half g_A[(size_t)LSEQ*RTOT];     // GEMM A (t,r)
__device__ __half g_B[(size_t)DDIM*RTOT];     // GEMM B (o,r)
__device__ float  g_part[3*(size_t)LSEQ*DDIM];// split-K partials

// ---------------- complex helpers ----------------
__device__ __forceinline__ float2 cmul(float2 a, float2 b) {
    return make_float2(a.x*b.x - a.y*b.y, a.x*b.y + a.y*b.x);
}
__device__ __forceinline__ float2 cadd(float2 a, float2 b){ return make_float2(a.x+b.x, a.y+b.y); }
__device__ __forceinline__ float2 csub(float2 a, float2 b){ return make_float2(a.x-b.x, a.y-b.y); }
template<int S> __device__ __forceinline__ float2 muli(float2 a) {   // a * (S*i)
    return (S > 0) ? make_float2(-a.y, a.x) : make_float2(a.y, -a.x);
}
__device__ __forceinline__ uint32_t s2u(const void* p) {
    uint32_t a;
    asm("{ .reg .u64 t; cvta.to.shared.u64 t, %1; cvt.u32.u64 %0, t; }" : "=r"(a) : "l"(p));
    return a;
}

// DFT8 in registers; S=-1 forward, +1 inverse. o[k] = sum_n v[n] e^{S*2pi i nk/8}
template<int S>
__device__ __forceinline__ void dft8(const float2 v[8], float2 o[8]) {
    const float h = 0.70710678118654752440f;
    float2 e0 = cadd(v[0], v[4]), e1 = csub(v[0], v[4]);
    float2 e2 = cadd(v[2], v[6]), e3 = csub(v[2], v[6]);
    float2 A0 = cadd(e0, e2), A2 = csub(e0, e2);
    float2 ie3 = muli<S>(e3);
    float2 A1 = cadd(e1, ie3), A3 = csub(e1, ie3);
    float2 q0 = cadd(v[1], v[5]), q1 = csub(v[1], v[5]);
    float2 q2 = cadd(v[3], v[7]), q3 = csub(v[3], v[7]);
    float2 B0 = cadd(q0, q2), B2 = csub(q0, q2);
    float2 iq3 = muli<S>(q3);
    float2 B1 = cadd(q1, iq3), B3 = csub(q1, iq3);
    B1 = make_float2(h*(B1.x - S*B1.y), h*(S*B1.x + B1.y));   // *E8^1
    B2 = muli<S>(B2);                                         // *E8^2
    B3 = make_float2(h*(-B3.x - S*B3.y), h*(S*B3.x - B3.y));  // *E8^3
    o[0] = cadd(A0, B0); o[4] = csub(A0, B0);
    o[1] = cadd(A1, B1); o[5] = csub(A1, B1);
    o[2] = cadd(A2, B2); o[6] = csub(A2, B2);
    o[3] = cadd(A3, B3); o[7] = csub(A3, B3);
}

__device__ __forceinline__ void twchain(float theta, float2 w[8]) {
    float sn, cs; __sincosf(theta, &sn, &cs);
    w[0] = make_float2(1.0f, 0.0f);
    w[1] = make_float2(cs, sn);
    #pragma unroll
    for (int m = 2; m < 8; m++) w[m] = cmul(w[m-1], w[1]);
}

#define FFT_SM 4608   // 4096 + pad: phys(p) = p + (p>>3)

// Forward radix-8 DIF after S0 regs preloaded+processed by caller? No: full device fn.
// v[j] = x[t + 512 j] on entry. Output o[m] = spectrum at digit-reversed position p = t*8+m.
__device__ __forceinline__ void fft8_fwd(float2* sm, int t, float2 v[8], float2 o[8]) {
    float2 w[8];
    // S0: stride 512
    dft8<-1>(v, o);
    twchain(-TWO_PI * (float)t / 4096.0f, w);
    int b0 = t + (t >> 3);
    sm[b0] = o[0];
    #pragma unroll
    for (int m = 1; m < 8; m++) sm[b0 + 576*m] = cmul(o[m], w[m]);
    __syncthreads();
    // S1: stride 64 within blocks of 512
    int blk = t >> 6, n1 = t & 63;
    int b1 = 576*blk + n1 + (n1 >> 3);
    #pragma unroll
    for (int j = 0; j < 8; j++) v[j] = sm[b1 + 72*j];
    dft8<-1>(v, o);
    twchain(-TWO_PI * (float)n1 / 512.0f, w);
    sm[b1] = o[0];
    #pragma unroll
    for (int m = 1; m < 8; m++) sm[b1 + 72*m] = cmul(o[m], w[m]);
    __syncthreads();
    // S2: stride 8 within blocks of 64
    int sb = t >> 3, n2 = t & 7;
    int b2 = 72*sb + n2;
    #pragma unroll
    for (int j = 0; j < 8; j++) v[j] = sm[b2 + 9*j];
    dft8<-1>(v, o);
    twchain(-TWO_PI * (float)n2 / 64.0f, w);
    sm[b2] = o[0];
    #pragma unroll
    for (int m = 1; m < 8; m++) sm[b2 + 9*m] = cmul(o[m], w[m]);
    __syncthreads();
    // S3: stride 1, no twiddle
    int b3 = 9*t;
    #pragma unroll
    for (int j = 0; j < 8; j++) v[j] = sm[b3 + j];
    dft8<-1>(v, o);
}

// Inverse radix-8 DIT. v[c] = Z at digit-reversed position p = t*8+c on entry.
// Output o[j] = time-domain x[t + 512 j] (unscaled; 1/N folded into V).
__device__ __forceinline__ void fft8_inv(float2* sm, int t, float2 v[8], float2 o[8]) {
    float2 w[8];
    // I0: undo S3 (register-local)
    dft8<1>(v, o);
    int b3 = 9*t;
    #pragma unroll
    for (int m = 0; m < 8; m++) sm[b3 + m] = o[m];
    __syncthreads();
    // I1: undo S2
    int sb = t >> 3, n2 = t & 7;
    int b2 = 72*sb + n2;
    twchain(TWO_PI * (float)n2 / 64.0f, w);
    #pragma unroll
    for (int m = 0; m < 8; m++) v[m] = cmul(sm[b2 + 9*m], w[m]);
    dft8<1>(v, o);
    #pragma unroll
    for (int m = 0; m < 8; m++) sm[b2 + 9*m] = o[m];
    __syncthreads();
    // I2: undo S1
    int blk = t >> 6, n1 = t & 63;
    int b1 = 576*blk + n1 + (n1 >> 3);
    twchain(TWO_PI * (float)n1 / 512.0f, w);
    #pragma unroll
    for (int m = 0; m < 8; m++) v[m] = cmul(sm[b1 + 72*m], w[m]);
    dft8<1>(v, o);
    #pragma unroll
    for (int m = 0; m < 8; m++) sm[b1 + 72*m] = o[m];
    __syncthreads();
    // I3: undo S0
    int b0 = t + (t >> 3);
    twchain(TWO_PI * (float)t / 4096.0f, w);
    #pragma unroll
    for (int m = 0; m < 8; m++) v[m] = cmul(sm[b0 + 576*m], w[m]);
    dft8<1>(v, o);
}

// ---------------- kernels ----------------

__global__ void transpose_kernel(const float* __restrict__ x) {
    __shared__ float tile[32][33];
    int t0 = blockIdx.x * 32;
    int d0 = blockIdx.y * 32;
    int tx = threadIdx.x, ty = threadIdx.y;
    #pragma unroll
    for (int s = 0; s < 32; s += 8)
        tile[ty + s][tx] = x[(t0 + ty + s) * DDIM + d0 + tx];
    __syncthreads();
    #pragma unroll
    for (int s = 0; s < 32; s += 8)
        g_xT[(size_t)(d0 + ty + s) * LSEQ + t0 + tx] = tile[tx][ty + s];
}

__global__ void __launch_bounds__(512) fft_x_kernel() {
    __shared__ float2 sm[FFT_SM];
    int d = blockIdx.x, t = threadIdx.x;
    float2 v[8], o[8];
    #pragma unroll
    for (int j = 0; j < 4; j++)
        v[j] = make_float2(g_xT[(size_t)d * LSEQ + t + 512*j], 0.0f);
    #pragma unroll
    for (int j = 4; j < 8; j++) v[j] = make_float2(0.0f, 0.0f);
    fft8_fwd(sm, t, v, o);
    float2* dst = g_Xf + (size_t)d * NFFT + t*8;
    #pragma unroll
    for (int m = 0; m < 8; m++) dst[m] = o[m];
}

__global__ void __launch_bounds__(512) fft_phi_kernel(const float* __restrict__ phi) {
    __shared__ float2 sm[FFT_SM];
    int k = blockIdx.x, t = threadIdx.x;
    float2 v[8], o[8];
    #pragma unroll
    for (int j = 0; j < 4; j++)
        v[j] = make_float2(phi[(t + 512*j) * KF + k], 0.0f);
    #pragma unroll
    for (int j = 4; j < 8; j++) v[j] = make_float2(0.0f, 0.0f);
    fft8_fwd(sm, t, v, o);
    const float sc = 1.0f / (float)NFFT;
    float2* dst = g_Vf + (size_t)k * NFFT + t*8;
    #pragma unroll
    for (int m = 0; m < 8; m++) dst[m] = make_float2(o[m].x * sc, o[m].y * sc);
}

// Per (k,d): comb[p] = V[p]*(X[p] + i*X[p^4]) in digit-reversed domain, then inverse FFT.
__global__ void __launch_bounds__(512) conv_ifft_kernel() {
    __shared__ float2 sm[FFT_SM];
    int b = blockIdx.x;
    int k = b / DDIM;
    int d = b - k*DDIM;
    int t = threadIdx.x;
    const float2* Xp = g_Xf + (size_t)d * NFFT + t*8;
    const float2* Vp = g_Vf + (size_t)k * NFFT + t*8;
    float2 X[8], v[8], o[8];
    #pragma unroll
    for (int c = 0; c < 8; c++) X[c] = Xp[c];
    #pragma unroll
    for (int c = 0; c < 8; c++) {
        float2 Xs = X[c ^ 4];
        float2 comb = make_float2(X[c].x - Xs.y, X[c].y + Xs.x);  // X + i*Xs
        v[c] = cmul(Vp[c], comb);
    }
    fft8_inv(sm, t, v, o);
    const size_t rowp = (size_t)(k*DDIM + d);
    const size_t rowm = (size_t)(KF*DDIM + k*DDIM + d);
    const float sg = (t & 1) ? -1.0f : 1.0f;    // (-1)^(t+512j) = (-1)^t
    #pragma unroll
    for (int j = 0; j < 4; j++) {
        int time = t + 512*j;
        g_Uch[rowp * LSEQ + time] = __float2half_rn(o[j].x);
        g_Uch[rowm * LSEQ + time] = __float2half_rn(o[j].y * sg);
    }
}

// Transpose fp16: g_Uch (r,t) -> g_A (t,r)
__global__ void ucatT_kernel() {
    __shared__ __half tile[32][33];
    int r0 = blockIdx.x * 32;
    int t0 = blockIdx.y * 32;
    int tx = threadIdx.x, ty = threadIdx.y;
    #pragma unroll
    for (int s = 0; s < 32; s += 8)
        tile[ty + s][tx] = g_Uch[(size_t)(r0 + ty + s) * LSEQ + t0 + tx];
    __syncthreads();
    #pragma unroll
    for (int s = 0; s < 32; s += 8)
        g_A[(size_t)(t0 + ty + s) * RTOT + r0 + tx] = tile[tx][ty + s];
}

__global__ void arfill_kernel(const float* __restrict__ x) {
    int idx = blockIdx.x * blockDim.x + threadIdx.x;
    if (idx >= LSEQ * KU * DDIM) return;
    int t   = idx / (KU * DDIM);
    int rem = idx - t * (KU * DDIM);
    int i   = rem / DDIM;
    int d   = rem - i * DDIM;
    float v = (t >= i) ? x[(size_t)(t - i) * DDIM + d] : 0.0f;
    g_A[(size_t)t * RTOT + RSPEC + (size_t)i * DDIM + d] = __float2half_rn(v);
}

__global__ void mcatT_kernel(const float* __restrict__ Mp,
                             const float* __restrict__ Mm,
                             const float* __restrict__ Mu,
                             const float* __restrict__ sigma) {
    __shared__ float tile[32][33];
    int r0 = blockIdx.x * 32;
    int o0 = blockIdx.y * 32;
    int tx = threadIdx.x, ty = threadIdx.y;
    #pragma unroll
    for (int s = 0; s < 32; s += 8) {
        int r = r0 + ty + s;
        int o = o0 + tx;
        float v;
        if (r < KF*DDIM) {
            v = Mp[(size_t)r * DDIM + o] * sqrtf(sqrtf(sigma[r / DDIM]));
        } else if (r < RSPEC) {
            int rr = r - KF*DDIM;
            v = Mm[(size_t)rr * DDIM + o] * sqrtf(sqrtf(sigma[rr / DDIM]));
        } else {
            v = Mu[(size_t)(r - RSPEC) * DDIM + o];
        }
        tile[ty + s][tx] = v;
    }
    __syncthreads();
    #pragma unroll
    for (int s = 0; s < 32; s += 8)
        g_B[(size_t)(o0 + ty + s) * RTOT + r0 + tx] = __float2half_rn(tile[tx][ty + s]);
}

// ---------------- fp16 mma.sync GEMM, split-K=3 ----------------
#define BM 128
#define BN 128
#define BK 32
#define KSPLIT 3
#define KLEN (RTOT/KSPLIT)      // 8960
#define NKI (KLEN/BK)           // 280
#define ASTRIDE 80
#define ATILEB (BM*ASTRIDE)     // 10240
#define BTILEB (BN*ASTRIDE)     // 10240
#define STAGEB (ATILEB + BTILEB)

__device__ __forceinline__ void cp16(uint32_t dst, const void* src) {
    asm volatile("cp.async.cg.shared.global [%0], [%1], 16;" :: "r"(dst), "l"(src));
}
#define LDSM4(R, addr) \
    asm volatile("ldmatrix.sync.aligned.m8n8.x4.shared.b16 {%0,%1,%2,%3}, [%4];" \
        : "=r"((R)[0]), "=r"((R)[1]), "=r"((R)[2]), "=r"((R)[3]) : "r"(addr))
#define MMA16816(C, A, B) \
    asm volatile("mma.sync.aligned.m16n8k16.row.col.f32.f16.f16.f32 " \
        "{%0,%1,%2,%3}, {%4,%5,%6,%7}, {%8,%9}, {%0,%1,%2,%3};" \
        : "+f"((C)[0]), "+f"((C)[1]), "+f"((C)[2]), "+f"((C)[3]) \
        : "r"((A)[0]), "r"((A)[1]), "r"((A)[2]), "r"((A)[3]), "r"((B)[0]), "r"((B)[1]))

__global__ void __launch_bounds__(256, 2) gemm_kernel() {
    __shared__ __align__(16) char sm[2*STAGEB];
    const int tid  = threadIdx.x;
    const int lane = tid & 31;
    const int wid  = tid >> 5;
    const int wm   = wid >> 2;     // 0..1 (m 64)
    const int wn   = wid & 3;      // 0..3 (n 32)
    const int t0   = blockIdx.x * BM;
    const int o0   = blockIdx.y * BN;
    const int ks   = blockIdx.z;
    const size_t koff = (size_t)ks * KLEN;
    const uint32_t sbase = s2u(sm);

    // cp.async mapping: 512 chunks each for A and B; id = c*128 + row
    const int ac0 = tid >> 7,        ar0 = tid & 127;
    const int ac1 = (tid + 256) >> 7, ar1 = tid & 127;   // tid+256: row = (tid+256)&127 = tid&127
    const __half* pA0 = g_A + (size_t)(t0 + ar0) * RTOT + koff + ac0*8;
    const __half* pA1 = g_A + (size_t)(t0 + ar1) * RTOT + koff + ac1*8;
    const uint32_t dA0 = (uint32_t)(ar0*ASTRIDE + ac0*16);
    const uint32_t dA1 = (uint32_t)(ar1*ASTRIDE + ac1*16);
    const __half* pB0 = g_B + (size_t)(o0 + ar0) * RTOT + koff + ac0*8;
    const __half* pB1 = g_B + (size_t)(o0 + ar1) * RTOT + koff + ac1*8;

    // ldmatrix lane offsets
    const int lrA = lane & 15;
    const int lcA = lane >> 4;
    const int grp = lane >> 3;
    const int rB = ((grp >> 1) << 3) + (lane & 7);   // 0..15
    const int cB = grp & 1;

    float acc[4][4][4];
    #pragma unroll
    for (int mi = 0; mi < 4; mi++)
        #pragma unroll
        for (int ni = 0; ni < 4; ni++)
            #pragma unroll
            for (int e = 0; e < 4; e++) acc[mi][ni][e] = 0.0f;

    {
        uint32_t s = sbase;
        cp16(s + dA0, pA0); cp16(s + dA1, pA1);
        cp16(s + ATILEB + dA0, pB0); cp16(s + ATILEB + dA1, pB1);
        asm volatile("cp.async.commit_group;");
    }

    #pragma unroll 1
    for (int c = 0; c < NKI; c++) {
        const int buf = c & 1;
        if (c + 1 < NKI) {
            size_t off = (size_t)(c + 1) * BK;
            uint32_t s = sbase + (buf ^ 1)*STAGEB;
            cp16(s + dA0, pA0 + off); cp16(s + dA1, pA1 + off);
            cp16(s + ATILEB + dA0, pB0 + off); cp16(s + ATILEB + dA1, pB1 + off);
            asm volatile("cp.async.commit_group;");
            asm volatile("cp.async.wait_group %0;" :: "n"(1));
        } else {
            asm volatile("cp.async.wait_group %0;" :: "n"(0));
        }
        __syncthreads();

        const uint32_t sA = sbase + buf*STAGEB;
        const uint32_t sB = sA + ATILEB;
        #pragma unroll
        for (int j = 0; j < 2; j++) {
            uint32_t a[4][4];
            #pragma unroll
            for (int mi = 0; mi < 4; mi++) {
                uint32_t addr = sA + (uint32_t)((wm*64 + mi*16 + lrA)*ASTRIDE + (2*j + lcA)*16);
                LDSM4(a[mi], addr);
            }
            uint32_t b[4][2];
            #pragma unroll
            for (int half = 0; half < 2; half++) {
                uint32_t addr = sB + (uint32_t)((wn*32 + half*16 + rB)*ASTRIDE + (2*j + cB)*16);
                uint32_t r4[4]; LDSM4(r4, addr);
                b[2*half][0]   = r4[0]; b[2*half][1]   = r4[1];
                b[2*half+1][0] = r4[2]; b[2*half+1][1] = r4[3];
            }
            #pragma unroll
            for (int mi = 0; mi < 4; mi++)
                #pragma unroll
                for (int ni = 0; ni < 4; ni++)
                    MMA16816(acc[mi][ni], a[mi], b[ni]);
        }
        __syncthreads();
    }

    float* pp = g_part + (size_t)ks * LSEQ * DDIM;
    const int row  = lane >> 2;
    const int col2 = (lane & 3) * 2;
    #pragma unroll
    for (int mi = 0; mi < 4; mi++) {
        #pragma unroll
        for (int ni = 0; ni < 4; ni++) {
            int t = t0 + wm*64 + mi*16 + row;
            int o = o0 + wn*32 + ni*8 + col2;
            float* p0 = pp + (size_t)t * DDIM + o;
            float* p1 = pp + (size_t)(t + 8) * DDIM + o;
            p0[0] = acc[mi][ni][0]; p0[1] = acc[mi][ni][1];
            p1[0] = acc[mi][ni][2]; p1[1] = acc[mi][ni][3];
        }
    }
}

__global__ void reduce_kernel(float* __restrict__ out) {
    int i = blockIdx.x * blockDim.x + threadIdx.x;   // float4 index
    const float4* p0 = (const float4*)g_part;
    const float4* p1 = (const float4*)(g_part + (size_t)LSEQ*DDIM);
    const float4* p2 = (const float4*)(g_part + 2*(size_t)LSEQ*DDIM);
    float4 a = p0[i], b = p1[i], c = p2[i];
    float4 r = make_float4(a.x+b.x+c.x, a.y+b.y+c.y, a.z+b.z+c.z, a.w+b.w+c.w);
    ((float4*)out)[i] = r;
}

// ---------------- launch ----------------
extern "C" void kernel_launch(void* const* d_in, const int* in_sizes, int n_in,
                              void* d_out, int out_size) {
    const float* x     = (const float*)d_in[0];
    const float* phi   = (const float*)d_in[1];
    const float* sigma = (const float*)d_in[2];
    const float* Mp    = (const float*)d_in[3];
    const float* Mm    = (const float*)d_in[4];
    const float* Mu    = (const float*)d_in[5];
    float* out = (float*)d_out;

    transpose_kernel<<<dim3(LSEQ/32, DDIM/32), dim3(32, 8)>>>(x);
    fft_x_kernel<<<DDIM, 512>>>();
    fft_phi_kernel<<<KF, 512>>>(phi);
    conv_ifft_kernel<<<KF*DDIM, 512>>>();
    ucatT_kernel<<<dim3(RSPEC/32, LSEQ/32), dim3(32, 8)>>>();
    arfill_kernel<<<(LSEQ*KU*DDIM + 255)/256, 256>>>(x);
    mcatT_kernel<<<dim3(RTOT/32, DDIM/32), dim3(32, 8)>>>(Mp, Mm, Mu, sigma);
    gemm_kernel<<<dim3(LSEQ/BM, DDIM/BN, KSPLIT), 256>>>();
    reduce_kernel<<<(LSEQ*DDIM/4 + 255)/256, 256>>>(out);
}